// round 9
// baseline (speedup 1.0000x reference)
#include <cuda_runtime.h>
#include <cstdint>

#define MM   128   // padded image side
#define NP   64    // patch side
#define NC   4     // channels / positions
#define C0   32    // (M - N) / 2
#define RB   8     // rows per thread (contiguous band)
#define BANDS_PER_IMG 4     // 4 CTAs per image, 16 output rows each
#define STAGE_FLOATS (16 * NP * NC)   // 4096 floats = 16KB per-CTA stage

__device__ __forceinline__ uint32_t smem_u32(const void* p) {
    uint32_t a;
    asm("{ .reg .u64 t; cvta.to.shared.u64 t, %1; cvt.u32.u64 %0, t; }"
        : "=r"(a) : "l"(p));
    return a;
}

// block (2, 64, 2): tx = channel pair, ty = output column, tz = 8-row sub-band.
// Each CTA computes a 16-row output band into a 16KB smem stage, then one
// elected thread issues a single cp.async.bulk (smem -> L2 direct, bypassing
// the L1/LSU store path entirely). Compute (regs 40) identical to R8.
__global__ __launch_bounds__(256, 6)
void extract_patches_kernel(const float* __restrict__ img,
                            const float* __restrict__ pos,
                            float* __restrict__ out)
{
    __shared__ __align__(16) float stage[STAGE_FLOATS];
    __shared__ float spos[2 * NC];

    const int b    = blockIdx.x >> 2;          // image index
    const int band = blockIdx.x & 3;           // 16-row band within the patch
    const float* I = img + (size_t)b * (MM * MM);

    const int lid = threadIdx.x + 2 * threadIdx.y + 128 * threadIdx.z;
    if (lid < 2 * NC)
        spos[lid] = pos[(size_t)b * (2 * NC) + lid];
    __syncthreads();

    const int col = threadIdx.y;                      // output column
    const int r0  = threadIdx.z * RB;                 // row within the band
    const int i0  = band * 16 + r0;                   // absolute output row
    const int cb  = threadIdx.x * 2;                  // first owned channel

    // Per-channel setup. wy hoisted to a band constant (validated R7/R8:
    // yy steps by exactly 1.0/row; bilinear continuity bounds error ~1e-6).
    float wx[2], wy[2], hprev[2];
    const float* base[2];
#pragma unroll
    for (int u = 0; u < 2; u++) {
        float ox = spos[cb + u];
        float oy = spos[NC + cb + u];

        float xx = (float)(col + C0) + ox;
        float x0 = floorf(xx);
        wx[u]    = xx - x0;
        int xi   = (int)x0;

        float yy = (float)(i0 + C0) + oy;
        float y0 = floorf(yy);
        wy[u]    = yy - y0;
        int yi   = (int)y0;

        // SHIFT_MAX=20, c0=32: xi in [12,51], deepest row access < 128 ->
        // the reference valid-mask is always true; no bounds checks.
        base[u] = I + yi * MM + xi;
        float a0 = __ldg(base[u]);
        float a1 = __ldg(base[u] + 1);
        hprev[u] = fmaf(a1 - a0, wx[u], a0);   // H(top row)
    }

    // Prefetch row 0's bottom taps.
    float nb0[2], nb1[2];
#pragma unroll
    for (int u = 0; u < 2; u++) {
        nb0[u] = __ldg(base[u] + MM);
        nb1[u] = __ldg(base[u] + MM + 1);
    }

    // Stage pointer: rows r0..r0+7 of this CTA's 16-row band.
    float* sb = stage + ((size_t)r0 * NP + col) * NC + cb;

#pragma unroll
    for (int k = 0; k < RB; k++) {
        float c00 = nb0[0], c01 = nb1[0];
        float c10 = nb0[1], c11 = nb1[1];

        if (k + 1 < RB) {   // depth-1 prefetch of next row's 4 taps
            nb0[0] = __ldg(base[0] + (k + 2) * MM);
            nb1[0] = __ldg(base[0] + (k + 2) * MM + 1);
            nb0[1] = __ldg(base[1] + (k + 2) * MM);
            nb1[1] = __ldg(base[1] + (k + 2) * MM + 1);
        }

        float2 res;
        {
            float hnew = fmaf(c01 - c00, wx[0], c00);
            res.x      = fmaf(hnew - hprev[0], wy[0], hprev[0]);
            hprev[0]   = hnew;
        }
        {
            float hnew = fmaf(c11 - c10, wx[1], c10);
            res.y      = fmaf(hnew - hprev[1], wy[1], hprev[1]);
            hprev[1]   = hnew;
        }
        // Conflict-free STS.64: warp writes one contiguous 256B smem run.
        *reinterpret_cast<float2*>(sb + (size_t)k * (NP * NC)) = res;
    }
    __syncthreads();

    // One elected thread bulk-stores the CTA's contiguous 16KB output band:
    // smem -> L2 direct (UBLKCP), zero L1 store wavefronts.
    if (lid == 0) {
        asm volatile("fence.proxy.async.shared::cta;" ::: "memory");
        float* gdst = out + (size_t)b * (NP * NP * NC) + (size_t)band * STAGE_FLOATS;
        asm volatile(
            "cp.async.bulk.global.shared::cta.bulk_group [%0], [%1], %2;"
            :: "l"(gdst), "r"(smem_u32(stage)), "n"(STAGE_FLOATS * 4)
            : "memory");
        asm volatile("cp.async.bulk.commit_group;" ::: "memory");
        asm volatile("cp.async.bulk.wait_group 0;" ::: "memory");
    }
}

extern "C" void kernel_launch(void* const* d_in, const int* in_sizes, int n_in,
                              void* d_out, int out_size)
{
    const float* img = (const float*)d_in[0];   // padded_obj (B,128,128,1)
    const float* pos = (const float*)d_in[1];   // positions  (B,1,2,4)
    float* out = (float*)d_out;                 // (B,64,64,4)

    int B = in_sizes[0] / (MM * MM);
    dim3 block(2, 64, 2);
    extract_patches_kernel<<<B * BANDS_PER_IMG, block>>>(img, pos, out);
}

// round 10
// speedup vs baseline: 1.0351x; 1.0351x over previous
#include <cuda_runtime.h>

#define MM   128   // padded image side
#define NP   64    // patch side
#define NC   4     // channels / positions
#define C0   32    // (M - N) / 2
#define RB   8     // rows per thread (contiguous band)
#define BANDS_PER_IMG 4   // 4 CTAs per image, 16 rows each (2 z-bands of 8)

// block (2, 64, 2): tx = channel pair (fastest -> warp float2 stores form one
// contiguous 256B full-sector run), ty = output column, tz = sub-band.
// A/B delta this round: default write-back stores (no __stcs) so L2 can
// accumulate and drain full lines in large bursts; branchless prefetch.
__global__ __launch_bounds__(256, 6)
void extract_patches_kernel(const float* __restrict__ img,
                            const float* __restrict__ pos,
                            float* __restrict__ out)
{
    const int b    = blockIdx.x >> 2;          // image index
    const int band = blockIdx.x & 3;           // 16-row band within the patch
    const float* I = img + (size_t)b * (MM * MM);

    // Stage the 8 position scalars: layout (B,1,2,C); dim0 = ox, dim1 = oy.
    __shared__ float spos[2 * NC];
    const int lid = threadIdx.x + 2 * threadIdx.y + 128 * threadIdx.z;
    if (lid < 2 * NC)
        spos[lid] = pos[(size_t)b * (2 * NC) + lid];
    __syncthreads();

    const int col = threadIdx.y;                      // output column
    const int i0  = band * 16 + threadIdx.z * RB;     // first row of band
    const int cb  = threadIdx.x * 2;                  // first owned channel

    // Per-channel setup. wy hoisted to a band constant (validated R7-R9:
    // yy steps by exactly 1.0/row; bilinear continuity bounds error ~1e-6).
    float wx[2], wy[2], hprev[2];
    const float* base[2];
#pragma unroll
    for (int u = 0; u < 2; u++) {
        float ox = spos[cb + u];
        float oy = spos[NC + cb + u];

        float xx = (float)(col + C0) + ox;
        float x0 = floorf(xx);
        wx[u]    = xx - x0;
        int xi   = (int)x0;

        float yy = (float)(i0 + C0) + oy;
        float y0 = floorf(yy);
        wy[u]    = yy - y0;
        int yi   = (int)y0;

        // SHIFT_MAX=20, c0=32: xi in [12,51], yi <= 108. Deepest access,
        // including the one-row prefetch overfetch, is row yi+RB+1 <= 118
        // and col xi+1 <= 52+64 < 128 -> reference valid-mask always true.
        base[u] = I + yi * MM + xi;
        float a0 = __ldg(base[u]);
        float a1 = __ldg(base[u] + 1);
        hprev[u] = fmaf(a1 - a0, wx[u], a0);   // H(top row)
    }

    // Prefetch row 0's bottom taps.
    float nb0[2], nb1[2];
#pragma unroll
    for (int u = 0; u < 2; u++) {
        nb0[u] = __ldg(base[u] + MM);
        nb1[u] = __ldg(base[u] + MM + 1);
    }

    // Output: (B, 64, 64, 4); channels cb..cb+1 at column `col`,
    // rows i0..i0+RB-1. Warp-contiguous full-sector float2 stores.
    float* ob = out + ((size_t)b * (NP * NP) + (size_t)i0 * NP + col) * NC + cb;

#pragma unroll
    for (int k = 0; k < RB; k++) {
        // Consume this row's prefetched taps.
        float c00 = nb0[0], c01 = nb1[0];
        float c10 = nb0[1], c11 = nb1[1];

        // Branchless depth-1 prefetch (last iteration overfetches one
        // in-bounds row that is simply unused).
        nb0[0] = __ldg(base[0] + (k + 2) * MM);
        nb1[0] = __ldg(base[0] + (k + 2) * MM + 1);
        nb0[1] = __ldg(base[1] + (k + 2) * MM);
        nb1[1] = __ldg(base[1] + (k + 2) * MM + 1);

        float2 res;
        {
            float hnew = fmaf(c01 - c00, wx[0], c00);
            res.x      = fmaf(hnew - hprev[0], wy[0], hprev[0]);
            hprev[0]   = hnew;
        }
        {
            float hnew = fmaf(c11 - c10, wx[1], c10);
            res.y      = fmaf(hnew - hprev[1], wy[1], hprev[1]);
            hprev[1]   = hnew;
        }
        // Default write-back store: let L2 coalesce full lines and drain
        // in large bursts (A/B against __stcs streaming policy).
        *reinterpret_cast<float2*>(ob + (size_t)k * (NP * NC)) = res;
    }
}

extern "C" void kernel_launch(void* const* d_in, const int* in_sizes, int n_in,
                              void* d_out, int out_size)
{
    const float* img = (const float*)d_in[0];   // padded_obj (B,128,128,1)
    const float* pos = (const float*)d_in[1];   // positions  (B,1,2,4)
    float* out = (float*)d_out;                 // (B,64,64,4)

    int B = in_sizes[0] / (MM * MM);
    dim3 block(2, 64, 2);
    extract_patches_kernel<<<B * BANDS_PER_IMG, block>>>(img, pos, out);
}

// round 11
// speedup vs baseline: 1.0461x; 1.0106x over previous
#include <cuda_runtime.h>
#include <cstdint>

#define MM    128   // padded image side
#define NP    64    // patch side
#define NC    4     // channels / positions
#define C0    32    // (M - N) / 2
#define RB    16    // rows per thread band
#define WROW0 11    // first staged image row
#define WROWS 108   // staged rows 11..118 (covers tap rows 12..116)
#define WCOL0 8     // first staged image col (16B-aligned float4 start)
#define WCOLS 112   // staged cols 8..119 (covers tap cols 12..115)

__device__ __forceinline__ uint32_t smem_u32(const void* p) {
    uint32_t a;
    asm("{ .reg .u64 t; cvta.to.shared.u64 t, %1; cvt.u32.u64 %0, t; }"
        : "=r"(a) : "l"(p));
    return a;
}

// One CTA per image. Phase 1: cp.async.cg streams the fixed 108x112 window
// (all possible taps for |shift|<20) into smem as full-line coalesced reads.
// Phase 2: bilinear taps from smem (LDS), warp-contiguous float2 write-back
// stores. This converts ALL DRAM reads from scattered sectors to streaming.
__global__ __launch_bounds__(512, 3)
void extract_patches_kernel(const float* __restrict__ img,
                            const float* __restrict__ pos,
                            float* __restrict__ out)
{
    __shared__ __align__(16) float stage[WROWS * WCOLS];   // 48384 B
    __shared__ float spos[2 * NC];

    const int b = blockIdx.x;
    const float* I = img + (size_t)b * (MM * MM);

    // block (2, 64, 4): tx = channel pair, ty = column, tz = 16-row band.
    const int lid = threadIdx.x + 2 * threadIdx.y + 128 * threadIdx.z;
    if (lid < 2 * NC)
        spos[lid] = pos[(size_t)b * (2 * NC) + lid];

    // ---- Phase 1: stream the window into smem (108 rows x 28 float4) ----
    {
        const int wid  = lid >> 5;     // 16 warps
        const int lane = lid & 31;
        if (lane < WCOLS / 4) {
            for (int r = wid; r < WROWS; r += 16) {
                uint32_t sdst = smem_u32(stage) + (r * WCOLS + lane * 4) * 4;
                const float* gsrc = I + (WROW0 + r) * MM + WCOL0 + lane * 4;
                asm volatile("cp.async.cg.shared.global [%0], [%1], 16;"
                             :: "r"(sdst), "l"(gsrc) : "memory");
            }
        }
        asm volatile("cp.async.commit_group;" ::: "memory");
        asm volatile("cp.async.wait_group 0;" ::: "memory");
    }
    __syncthreads();

    const int col = threadIdx.y;          // output column j in [0, 64)
    const int i0  = threadIdx.z * RB;     // first row of this thread's band
    const int cb  = threadIdx.x * 2;      // first of this thread's 2 channels

    // Per-channel setup. wy hoisted to a band constant (validated R7-R10:
    // yy steps by exactly 1.0/row; bilinear continuity bounds error ~1e-6).
    float wx[2], wy[2], hprev[2];
    int sb[2];
#pragma unroll
    for (int u = 0; u < 2; u++) {
        float ox = spos[cb + u];
        float oy = spos[NC + cb + u];

        float xx = (float)(col + C0) + ox;
        float x0 = floorf(xx);
        wx[u]    = xx - x0;
        int xi   = (int)x0;

        float yy = (float)(i0 + C0) + oy;
        float y0 = floorf(yy);
        wy[u]    = yy - y0;
        int yi   = (int)y0;

        // |shift|<20, c0=32: yi in [12,99], xi in [12,114]; staged window
        // rows 11..118 / cols 8..119 covers all taps incl. yi+RB, xi+1.
        sb[u] = (yi - WROW0) * WCOLS + (xi - WCOL0);
        float a0 = stage[sb[u]];
        float a1 = stage[sb[u] + 1];
        hprev[u] = fmaf(a1 - a0, wx[u], a0);   // H(top row)
    }

    // Output: (B, 64, 64, 4); channels cb..cb+1 at column `col`,
    // rows i0..i0+RB-1. Warp-contiguous full-sector float2 stores.
    float* ob = out + ((size_t)b * (NP * NP) + (size_t)i0 * NP + col) * NC + cb;

#pragma unroll
    for (int k = 0; k < RB; k++) {
        float2 res;
#pragma unroll
        for (int u = 0; u < 2; u++) {
            int idx = sb[u] + (k + 1) * WCOLS;
            float b0 = stage[idx];
            float b1 = stage[idx + 1];
            float hnew = fmaf(b1 - b0, wx[u], b0);      // H(bottom row)
            float r    = fmaf(hnew - hprev[u], wy[u], hprev[u]);
            hprev[u]   = hnew;
            if (u == 0) res.x = r; else res.y = r;
        }
        // Write-back store (R10 winner): L2 coalesces full lines.
        *reinterpret_cast<float2*>(ob + (size_t)k * (NP * NC)) = res;
    }
}

extern "C" void kernel_launch(void* const* d_in, const int* in_sizes, int n_in,
                              void* d_out, int out_size)
{
    const float* img = (const float*)d_in[0];   // padded_obj (B,128,128,1)
    const float* pos = (const float*)d_in[1];   // positions  (B,1,2,4)
    float* out = (float*)d_out;                 // (B,64,64,4)

    int B = in_sizes[0] / (MM * MM);
    dim3 block(2, 64, 4);
    extract_patches_kernel<<<B, block>>>(img, pos, out);
}

// round 12
// speedup vs baseline: 1.0951x; 1.0468x over previous
#include <cuda_runtime.h>
#include <cstdint>

#define MM    128   // padded image side
#define NP    64    // patch side
#define NC    4     // channels / positions
#define C0    32    // (M - N) / 2
#define RB    16    // rows per thread band
#define WROW0 11    // first staged image row (fixed layout, as R11)
#define WROWS 108   // stage capacity rows 11..118
#define WCOL0 8     // first staged image col (16B-aligned)
#define WCOLS 112   // stage capacity cols 8..119

__device__ __forceinline__ uint32_t smem_u32(const void* p) {
    uint32_t a;
    asm("{ .reg .u64 t; cvta.to.shared.u64 t, %1; cvt.u32.u64 %0, t; }"
        : "=r"(a) : "l"(p));
    return a;
}

// One CTA per image, R11 structure, with DYNAMIC window bounds: positions are
// known at kernel start, so only the rows / 16B col-chunks actually reachable
// by this image's four shift vectors are streamed into smem (expected ~74% of
// the fixed window). Stage layout & compute phase identical to R11.
__global__ __launch_bounds__(512, 3)
void extract_patches_kernel(const float* __restrict__ img,
                            const float* __restrict__ pos,
                            float* __restrict__ out)
{
    __shared__ __align__(16) float stage[WROWS * WCOLS];   // 48384 B

    const int b = blockIdx.x;
    const float* I = img + (size_t)b * (MM * MM);
    const float* P = pos + (size_t)b * (2 * NC);

    // Every thread reads the 8 position scalars (uniform -> broadcast loads)
    // and derives identical window bounds; no staging/sync needed.
    float oxv[NC], oyv[NC];
    int ymin = MM, ymax = 0, xmin = MM, xmax = 0;
#pragma unroll
    for (int c = 0; c < NC; c++) {
        oxv[c] = __ldg(P + c);
        oyv[c] = __ldg(P + NC + c);
        // Base integer offsets at (row 0 / col 0); per-element floors can
        // deviate by +/-1 ulp-rounding, so pad one cell each side.
        int yb = (int)floorf((float)C0 + oyv[c]);
        int xb = (int)floorf((float)C0 + oxv[c]);
        ymin = min(ymin, yb - 1);  ymax = max(ymax, yb + NP + 1);
        xmin = min(xmin, xb - 1);  xmax = max(xmax, xb + NP + 1);
    }
    // |shift|<20 -> ymin,xmin >= 11, ymax,xmax <= 117: inside fixed stage.

    const int lid = threadIdx.x + 2 * threadIdx.y + 128 * threadIdx.z;

    // ---- Phase 1: stream only the needed sub-window (full-line reads) ----
    {
        const int wid  = lid >> 5;     // 16 warps
        const int lane = lid & 31;
        const int r_lo = ymin - WROW0;
        const int r_hi = ymax - WROW0;            // inclusive
        const int q_lo = (xmin - WCOL0) >> 2;     // first float4 chunk
        const int q_hi = (xmax - WCOL0) >> 2;     // last float4 chunk
        if (lane >= q_lo && lane <= q_hi) {
            for (int r = r_lo + wid; r <= r_hi; r += 16) {
                uint32_t sdst = smem_u32(stage) + (r * WCOLS + lane * 4) * 4;
                const float* gsrc = I + (WROW0 + r) * MM + WCOL0 + lane * 4;
                asm volatile("cp.async.cg.shared.global [%0], [%1], 16;"
                             :: "r"(sdst), "l"(gsrc) : "memory");
            }
        }
        asm volatile("cp.async.commit_group;" ::: "memory");
        asm volatile("cp.async.wait_group 0;" ::: "memory");
    }
    __syncthreads();

    // block (2, 64, 4): tx = channel pair, ty = column, tz = 16-row band.
    const int col = threadIdx.y;
    const int i0  = threadIdx.z * RB;
    const int cb  = threadIdx.x * 2;

    // Per-channel setup. wy hoisted to a band constant (validated R7-R11).
    float wx[2], wy[2], hprev[2];
    int sb[2];
#pragma unroll
    for (int u = 0; u < 2; u++) {
        float ox = oxv[cb + u];
        float oy = oyv[cb + u];

        float xx = (float)(col + C0) + ox;
        float x0 = floorf(xx);
        wx[u]    = xx - x0;
        int xi   = (int)x0;

        float yy = (float)(i0 + C0) + oy;
        float y0 = floorf(yy);
        wy[u]    = yy - y0;
        int yi   = (int)y0;

        sb[u] = (yi - WROW0) * WCOLS + (xi - WCOL0);
        float a0 = stage[sb[u]];
        float a1 = stage[sb[u] + 1];
        hprev[u] = fmaf(a1 - a0, wx[u], a0);   // H(top row)
    }

    // Output: (B, 64, 64, 4); warp-contiguous full-sector float2 stores.
    float* ob = out + ((size_t)b * (NP * NP) + (size_t)i0 * NP + col) * NC + cb;

#pragma unroll
    for (int k = 0; k < RB; k++) {
        float2 res;
#pragma unroll
        for (int u = 0; u < 2; u++) {
            int idx = sb[u] + (k + 1) * WCOLS;
            float b0 = stage[idx];
            float b1 = stage[idx + 1];
            float hnew = fmaf(b1 - b0, wx[u], b0);      // H(bottom row)
            float r    = fmaf(hnew - hprev[u], wy[u], hprev[u]);
            hprev[u]   = hnew;
            if (u == 0) res.x = r; else res.y = r;
        }
        // Write-back store (R10/R11 winner): L2 coalesces full lines.
        *reinterpret_cast<float2*>(ob + (size_t)k * (NP * NC)) = res;
    }
}

extern "C" void kernel_launch(void* const* d_in, const int* in_sizes, int n_in,
                              void* d_out, int out_size)
{
    const float* img = (const float*)d_in[0];   // padded_obj (B,128,128,1)
    const float* pos = (const float*)d_in[1];   // positions  (B,1,2,4)
    float* out = (float*)d_out;                 // (B,64,64,4)

    int B = in_sizes[0] / (MM * MM);
    dim3 block(2, 64, 4);
    extract_patches_kernel<<<B, block>>>(img, pos, out);
}